// round 5
// baseline (speedup 1.0000x reference)
#include <cuda_runtime.h>
#include <math.h>

#define N_NODES 50000
#define N_EDGES 500000
#define HID 128
#define NHEAD 4
#define TM 64            // rows per block in GEMM kernels
#define TPAD 66          // padded row length for transposed smem tile (even!)

typedef unsigned long long u64;

// ---------------- scratch (device globals; no allocations allowed) ----------
__device__ float g_xsrc[N_NODES * HID];
__device__ float g_xdst[N_NODES * HID];
__device__ float g_agg[N_NODES * HID];     // NORMALIZED aggregated messages
__device__ float g_gamma[HID];             // 1 + 0.5*tanh(gamma)
__device__ float g_beta[HID];
__device__ int   g_deg[N_NODES];           // degree histogram
__device__ int   g_pos[N_NODES];           // scatter cursors
__device__ int   g_off[N_NODES + 1];       // CSR offsets
__device__ int   g_pk[N_EDGES];            // packed (etype<<20)|src per edge
__device__ int   g_part[64];               // scan partials

// ---------------- f32x2 helpers ----------------------------------------------
__device__ __forceinline__ u64 pk2(float lo, float hi) {
    u64 r;
    asm("mov.b64 %0, {%1, %2};" : "=l"(r) : "f"(lo), "f"(hi));
    return r;
}
__device__ __forceinline__ u64 fma2(u64 a, u64 b, u64 c) {
    u64 d;
    asm("fma.rn.f32x2 %0, %1, %2, %3;" : "=l"(d) : "l"(a), "l"(b), "l"(c));
    return d;
}
__device__ __forceinline__ void unpk2(u64 a, float& lo, float& hi) {
    asm("mov.b64 {%0, %1}, %2;" : "=f"(lo), "=f"(hi) : "l"(a));
}

// ---------------- K1: x_src/x_dst projections + degree histogram -------------
// 512 threads, smem = Ws(64K)+Wd(64K)+tile(33K) -> 1 CTA/SM, 16 warps
__global__ void __launch_bounds__(512, 1) k_proj(
    const float* __restrict__ x,
    const float* __restrict__ Wsrc, const float* __restrict__ bsrc,
    const float* __restrict__ Wdst, const float* __restrict__ bdst,
    const int* __restrict__ dst, int n_nodes, int n_edges)
{
    extern __shared__ float sm[];
    float* Ws_s = sm;                 // 16384 floats
    float* Wd_s = sm + 16384;         // 16384 floats
    float* shx  = sm + 32768;         // [HID][TPAD] transposed x tile
    int tid = threadIdx.x;
    int tx = tid & 31;                // cols tx*4 .. tx*4+3
    int ty = tid >> 5;                // rows ty*4 .. ty*4+3
    int base = blockIdx.x * TM;

    const float4* Wsg = (const float4*)Wsrc;
    const float4* Wdg = (const float4*)Wdst;
    #pragma unroll
    for (int i = tid; i < 4096; i += 512) {
        ((float4*)Ws_s)[i] = __ldg(&Wsg[i]);
        ((float4*)Wd_s)[i] = __ldg(&Wdg[i]);
    }
    for (int i = tid; i < TM * 32; i += 512) {
        int r  = i >> 5;
        int c4 = (i & 31) * 4;
        int row = base + r;
        float4 v = make_float4(0.f, 0.f, 0.f, 0.f);
        if (row < n_nodes) v = *(const float4*)&x[(size_t)row * HID + c4];
        shx[(c4 + 0) * TPAD + r] = v.x; shx[(c4 + 1) * TPAD + r] = v.y;
        shx[(c4 + 2) * TPAD + r] = v.z; shx[(c4 + 3) * TPAD + r] = v.w;
    }
    __syncthreads();

    u64 as[2][4], ad[2][4];
    #pragma unroll
    for (int p = 0; p < 2; p++)
        #pragma unroll
        for (int c = 0; c < 4; c++) { as[p][c] = 0ull; ad[p][c] = 0ull; }

    int r0 = ty * 4;

    #pragma unroll 4
    for (int k = 0; k < HID; k++) {
        float4 ws = *(const float4*)&Ws_s[k * HID + tx * 4];
        float4 wd = *(const float4*)&Wd_s[k * HID + tx * 4];
        u64 x2[2];
        x2[0] = *(const u64*)&shx[k * TPAD + r0];
        x2[1] = *(const u64*)&shx[k * TPAD + r0 + 2];
        u64 s0 = pk2(ws.x, ws.x), s1 = pk2(ws.y, ws.y),
            s2 = pk2(ws.z, ws.z), s3 = pk2(ws.w, ws.w);
        u64 d0 = pk2(wd.x, wd.x), d1 = pk2(wd.y, wd.y),
            d2 = pk2(wd.z, wd.z), d3 = pk2(wd.w, wd.w);
        #pragma unroll
        for (int p = 0; p < 2; p++) {
            as[p][0] = fma2(x2[p], s0, as[p][0]);
            as[p][1] = fma2(x2[p], s1, as[p][1]);
            as[p][2] = fma2(x2[p], s2, as[p][2]);
            as[p][3] = fma2(x2[p], s3, as[p][3]);
            ad[p][0] = fma2(x2[p], d0, ad[p][0]);
            ad[p][1] = fma2(x2[p], d1, ad[p][1]);
            ad[p][2] = fma2(x2[p], d2, ad[p][2]);
            ad[p][3] = fma2(x2[p], d3, ad[p][3]);
        }
    }

    int col4 = tx * 4;
    float4 bs4 = __ldg(&((const float4*)bsrc)[tx]);
    float4 bd4 = __ldg(&((const float4*)bdst)[tx]);
    #pragma unroll
    for (int p = 0; p < 2; p++) {
        #pragma unroll
        for (int h = 0; h < 2; h++) {
            int row = base + r0 + 2 * p + h;
            if (row >= n_nodes) continue;
            float4 os, od; float lo, hi;
            unpk2(as[p][0], lo, hi); os.x = (h ? hi : lo) + bs4.x;
            unpk2(as[p][1], lo, hi); os.y = (h ? hi : lo) + bs4.y;
            unpk2(as[p][2], lo, hi); os.z = (h ? hi : lo) + bs4.z;
            unpk2(as[p][3], lo, hi); os.w = (h ? hi : lo) + bs4.w;
            unpk2(ad[p][0], lo, hi); od.x = (h ? hi : lo) + bd4.x;
            unpk2(ad[p][1], lo, hi); od.y = (h ? hi : lo) + bd4.y;
            unpk2(ad[p][2], lo, hi); od.z = (h ? hi : lo) + bd4.z;
            unpk2(ad[p][3], lo, hi); od.w = (h ? hi : lo) + bd4.w;
            *(float4*)&g_xsrc[(size_t)row * HID + col4] = os;
            *(float4*)&g_xdst[(size_t)row * HID + col4] = od;
        }
    }

    // degree histogram (independent of GEMM stores, grid-stride)
    for (int i = blockIdx.x * 512 + tid; i < n_edges; i += gridDim.x * 512)
        atomicAdd(&g_deg[__ldg(dst + i)], 1);
}

// ---------------- scan kernels for CSR offsets --------------------------------
__global__ void k_scan1(int n_nodes) {
    int idx = blockIdx.x * 1024 + threadIdx.x;
    int lane = threadIdx.x & 31, w = threadIdx.x >> 5;
    int v = (idx < n_nodes) ? g_deg[idx] : 0;
    int x = v;
    #pragma unroll
    for (int off = 1; off < 32; off <<= 1) {
        int y = __shfl_up_sync(0xffffffffu, x, off);
        if (lane >= off) x += y;
    }
    __shared__ int ws[32];
    if (lane == 31) ws[w] = x;
    __syncthreads();
    if (w == 0) {
        int s = ws[lane];
        #pragma unroll
        for (int off = 1; off < 32; off <<= 1) {
            int y = __shfl_up_sync(0xffffffffu, s, off);
            if (lane >= off) s += y;
        }
        ws[lane] = s;
    }
    __syncthreads();
    int incl = x + (w > 0 ? ws[w - 1] : 0);
    if (idx < n_nodes) g_off[idx + 1] = incl;
    if (threadIdx.x == 1023) g_part[blockIdx.x] = incl;
}

__global__ void k_scan2(int n_nodes) {
    int b = blockIdx.x;
    __shared__ int pre;
    if (threadIdx.x == 0) {
        int s = 0;
        for (int j = 0; j < b; j++) s += g_part[j];
        pre = s;
        if (b == 0) g_off[0] = 0;
    }
    __syncthreads();
    int idx = b * 1024 + threadIdx.x;
    if (idx < n_nodes) g_off[idx + 1] += pre;
}

// ---------------- scatter edges into CSR buckets -------------------------------
__global__ void k_scatter(const int* __restrict__ src, const int* __restrict__ dst,
                          const int* __restrict__ et, int n_edges)
{
    int e = blockIdx.x * blockDim.x + threadIdx.x;
    if (e >= n_edges) return;
    int d = __ldg(dst + e);
    int p = atomicAdd(&g_pos[d], 1);
    g_pk[g_off[d] + p] = __ldg(src + e) | (__ldg(et + e) << 20);
}

// ---------------- Kf: FiLM params -------------------------------------------
__global__ void k_film(const float* __restrict__ task,
                       const float* __restrict__ Wf,
                       const float* __restrict__ bf)
{
    int j = threadIdx.x;  // 256 threads
    float acc = bf[j];
    for (int k = 0; k < HID; k++)
        acc = fmaf(task[k], Wf[k * 2 * HID + j], acc);
    if (j < HID) g_gamma[j] = 1.0f + 0.5f * tanhf(acc);
    else         g_beta[j - HID] = acc;
}

// ---------------- K2: CSR edge pass, warp per destination node ---------------
// For each dst node: load x_dst once, loop incoming edges, keep softmax sum in
// registers, write normalized agg with one store. No float atomics anywhere.
__global__ void __launch_bounds__(256) k_edge(
    const float* __restrict__ edge_emb, const float* __restrict__ att,
    int n_nodes)
{
    int node = (blockIdx.x * blockDim.x + threadIdx.x) >> 5;
    int lane = threadIdx.x & 31;
    if (node >= n_nodes) return;

    float4 w  = __ldg(&((const float4*)att)[lane]);
    float4 xd = *(const float4*)&g_xdst[(size_t)node * HID + lane * 4];

    int beg = g_off[node], end = g_off[node + 1];
    const float4* xsg = (const float4*)g_xsrc;
    const float4* eeg = (const float4*)edge_emb;

    float4 acc = make_float4(0.f, 0.f, 0.f, 0.f);
    float  ssum = 0.0f;

    int pk_next = (beg < end) ? __ldg(&g_pk[beg]) : 0;
    for (int e = beg; e < end; e++) {
        int pk = pk_next;
        if (e + 1 < end) pk_next = __ldg(&g_pk[e + 1]);
        int s = pk & 0xFFFFF;
        int t = pk >> 20;
        float4 a = __ldg(&xsg[(size_t)s * 32 + lane]);
        float4 c = __ldg(&eeg[t * 32 + lane]);

        float v0 = a.x + xd.x + c.x; v0 = (v0 > 0.0f) ? v0 : 0.2f * v0;
        float v1 = a.y + xd.y + c.y; v1 = (v1 > 0.0f) ? v1 : 0.2f * v1;
        float v2 = a.z + xd.z + c.z; v2 = (v2 > 0.0f) ? v2 : 0.2f * v2;
        float v3 = a.w + xd.w + c.w; v3 = (v3 > 0.0f) ? v3 : 0.2f * v3;
        float p = fmaf(v0, w.x, fmaf(v1, w.y, fmaf(v2, w.z, v3 * w.w)));

        p += __shfl_xor_sync(0xffffffffu, p, 4);
        p += __shfl_xor_sync(0xffffffffu, p, 2);
        p += __shfl_xor_sync(0xffffffffu, p, 1);
        // all 8 lanes of this head group now hold the head logit
        float ex = __expf(p);
        ssum += ex;
        acc.x = fmaf(a.x, ex, acc.x);
        acc.y = fmaf(a.y, ex, acc.y);
        acc.z = fmaf(a.z, ex, acc.z);
        acc.w = fmaf(a.w, ex, acc.w);
    }

    float inv = 1.0f / fmaxf(ssum, 1e-12f);
    float4 o;
    o.x = acc.x * inv; o.y = acc.y * inv;
    o.z = acc.z * inv; o.w = acc.w * inv;
    *(float4*)&g_agg[(size_t)node * HID + lane * 4] = o;
}

// ---------------- K5: out = LN(node + FiLM(agg@W_out+b)) ---------------------
// 512 threads, smem = W(64K)+tile(33K) -> 2 CTAs/SM, 32 warps
__global__ void __launch_bounds__(512, 2) k_out(
    const float* __restrict__ node,
    const float* __restrict__ Wout, const float* __restrict__ bout,
    const float* __restrict__ normw, const float* __restrict__ normb,
    float* __restrict__ out, int n_nodes)
{
    extern __shared__ float sm[];
    float* W_s = sm;                  // 16384 floats
    float* shx = sm + 16384;          // [HID][TPAD] transposed tile
    int tid = threadIdx.x;
    int tx = tid & 31;
    int ty = tid >> 5;                // 0..15
    int base = blockIdx.x * TM;

    const float4* Wg = (const float4*)Wout;
    #pragma unroll
    for (int i = tid; i < 4096; i += 512)
        ((float4*)W_s)[i] = __ldg(&Wg[i]);

    for (int i = tid; i < TM * 32; i += 512) {
        int r  = i >> 5;
        int c4 = (i & 31) * 4;
        int row = base + r;
        float4 v = make_float4(0.f, 0.f, 0.f, 0.f);
        if (row < n_nodes) v = *(const float4*)&g_agg[(size_t)row * HID + c4];
        shx[(c4 + 0) * TPAD + r] = v.x; shx[(c4 + 1) * TPAD + r] = v.y;
        shx[(c4 + 2) * TPAD + r] = v.z; shx[(c4 + 3) * TPAD + r] = v.w;
    }
    __syncthreads();

    u64 acc[2][4];
    #pragma unroll
    for (int p = 0; p < 2; p++)
        #pragma unroll
        for (int c = 0; c < 4; c++) acc[p][c] = 0ull;

    int r0 = ty * 4;

    #pragma unroll 4
    for (int k = 0; k < HID; k++) {
        float4 w = *(const float4*)&W_s[k * HID + tx * 4];
        u64 x2[2];
        x2[0] = *(const u64*)&shx[k * TPAD + r0];
        x2[1] = *(const u64*)&shx[k * TPAD + r0 + 2];
        u64 w0 = pk2(w.x, w.x), w1 = pk2(w.y, w.y),
            w2 = pk2(w.z, w.z), w3 = pk2(w.w, w.w);
        #pragma unroll
        for (int p = 0; p < 2; p++) {
            acc[p][0] = fma2(x2[p], w0, acc[p][0]);
            acc[p][1] = fma2(x2[p], w1, acc[p][1]);
            acc[p][2] = fma2(x2[p], w2, acc[p][2]);
            acc[p][3] = fma2(x2[p], w3, acc[p][3]);
        }
    }

    // epilogue: FiLM + residual + LayerNorm, all within the warp
    int col4 = tx * 4;
    float4 bo4 = __ldg(&((const float4*)bout)[tx]);
    float4 gm4 = *(const float4*)&g_gamma[col4];
    float4 bt4 = *(const float4*)&g_beta[col4];
    float4 nw4 = __ldg(&((const float4*)normw)[tx]);
    float4 nb4 = __ldg(&((const float4*)normb)[tx]);

    #pragma unroll
    for (int p = 0; p < 2; p++) {
        #pragma unroll
        for (int h = 0; h < 2; h++) {
            int row = base + r0 + 2 * p + h;
            bool ok = (row < n_nodes);
            float4 nd = make_float4(0.f, 0.f, 0.f, 0.f);
            if (ok) nd = *(const float4*)&node[(size_t)row * HID + col4];
            float lo, hi, y0, y1, y2, y3;
            unpk2(acc[p][0], lo, hi); y0 = nd.x + ((h ? hi : lo) + bo4.x) * gm4.x + bt4.x;
            unpk2(acc[p][1], lo, hi); y1 = nd.y + ((h ? hi : lo) + bo4.y) * gm4.y + bt4.y;
            unpk2(acc[p][2], lo, hi); y2 = nd.z + ((h ? hi : lo) + bo4.z) * gm4.z + bt4.z;
            unpk2(acc[p][3], lo, hi); y3 = nd.w + ((h ? hi : lo) + bo4.w) * gm4.w + bt4.w;

            float s1 = y0 + y1 + y2 + y3;
            float s2 = y0 * y0 + y1 * y1 + y2 * y2 + y3 * y3;
            #pragma unroll
            for (int off = 16; off; off >>= 1) {
                s1 += __shfl_xor_sync(0xffffffffu, s1, off);
                s2 += __shfl_xor_sync(0xffffffffu, s2, off);
            }
            float mu  = s1 * (1.0f / HID);
            float var = s2 * (1.0f / HID) - mu * mu;
            float inv = rsqrtf(var + 1e-5f);
            if (ok) {
                float4 o;
                o.x = (y0 - mu) * inv * nw4.x + nb4.x;
                o.y = (y1 - mu) * inv * nw4.y + nb4.y;
                o.z = (y2 - mu) * inv * nw4.z + nb4.z;
                o.w = (y3 - mu) * inv * nw4.w + nb4.w;
                *(float4*)&out[(size_t)row * HID + col4] = o;
            }
        }
    }
}

// ---------------- launch -----------------------------------------------------
extern "C" void kernel_launch(void* const* d_in, const int* in_sizes, int n_in,
                              void* d_out, int out_size)
{
    const float* node   = (const float*)d_in[0];
    const int*   eidx   = (const int*)  d_in[1];
    const int*   etype  = (const int*)  d_in[2];
    const float* task   = (const float*)d_in[3];
    const float* Wsrc   = (const float*)d_in[4];
    const float* bsrc   = (const float*)d_in[5];
    const float* Wdst   = (const float*)d_in[6];
    const float* bdst   = (const float*)d_in[7];
    const float* eemb   = (const float*)d_in[8];
    const float* att    = (const float*)d_in[9];
    const float* Wout   = (const float*)d_in[10];
    const float* bout   = (const float*)d_in[11];
    const float* normw  = (const float*)d_in[12];
    const float* normb  = (const float*)d_in[13];
    const float* Wfilm  = (const float*)d_in[14];
    const float* bfilm  = (const float*)d_in[15];
    float* out = (float*)d_out;

    int n_nodes = in_sizes[0] / HID;
    int n_edges = in_sizes[2];
    const int* src = eidx;
    const int* dst = eidx + n_edges;

    void* p_deg = nullptr; void* p_pos = nullptr;
    cudaGetSymbolAddress(&p_deg, g_deg);
    cudaGetSymbolAddress(&p_pos, g_pos);
    cudaMemsetAsync(p_deg, 0, (size_t)n_nodes * sizeof(int));
    cudaMemsetAsync(p_pos, 0, (size_t)n_nodes * sizeof(int));

    const int smem_proj = (2 * 16384 + HID * TPAD) * sizeof(float);  // ~164KB
    const int smem_out  = (16384 + HID * TPAD) * sizeof(float);      // ~99KB
    cudaFuncSetAttribute(k_proj, cudaFuncAttributeMaxDynamicSharedMemorySize, smem_proj);
    cudaFuncSetAttribute(k_out,  cudaFuncAttributeMaxDynamicSharedMemorySize, smem_out);

    int gblk = (n_nodes + TM - 1) / TM;
    int nsb  = (n_nodes + 1023) / 1024;

    k_proj<<<gblk, 512, smem_proj>>>(node, Wsrc, bsrc, Wdst, bdst, dst,
                                     n_nodes, n_edges);
    k_scan1<<<nsb, 1024>>>(n_nodes);
    k_scan2<<<nsb, 1024>>>(n_nodes);
    k_scatter<<<(n_edges + 255) / 256, 256>>>(src, dst, etype, n_edges);
    k_film<<<1, 2 * HID>>>(task, Wfilm, bfilm);
    k_edge<<<(n_nodes * 32 + 255) / 256, 256>>>(eemb, att, n_nodes);
    k_out<<<gblk, 512, smem_out>>>(node, Wout, bout, normw, normb, out, n_nodes);
}

// round 6
// speedup vs baseline: 1.0052x; 1.0052x over previous
#include <cuda_runtime.h>
#include <math.h>

#define N_NODES 50000
#define N_EDGES 500000
#define HID 128
#define NHEAD 4
#define TM 64            // rows per block in GEMM kernels
#define TPAD 66          // padded row length for transposed smem tile (even!)

typedef unsigned long long u64;

// ---------------- scratch (device globals; no allocations allowed) ----------
__device__ float g_xsrc[N_NODES * HID];
__device__ float g_xdst[N_NODES * HID];
__device__ float g_agg[N_NODES * HID];     // NORMALIZED aggregated messages
__device__ float g_gamma[HID];             // 1 + 0.5*tanh(gamma)
__device__ float g_beta[HID];
__device__ int   g_deg[N_NODES];           // degree histogram
__device__ int   g_pos[N_NODES];           // scatter cursors
__device__ int   g_off[N_NODES + 1];       // CSR offsets
__device__ int   g_pk[N_EDGES];            // packed (etype<<20)|src per edge
__device__ int   g_part[64];               // scan partials

// ---------------- f32x2 helpers ----------------------------------------------
__device__ __forceinline__ u64 pk2(float lo, float hi) {
    u64 r;
    asm("mov.b64 %0, {%1, %2};" : "=l"(r) : "f"(lo), "f"(hi));
    return r;
}
__device__ __forceinline__ u64 fma2(u64 a, u64 b, u64 c) {
    u64 d;
    asm("fma.rn.f32x2 %0, %1, %2, %3;" : "=l"(d) : "l"(a), "l"(b), "l"(c));
    return d;
}
__device__ __forceinline__ void unpk2(u64 a, float& lo, float& hi) {
    asm("mov.b64 {%0, %1}, %2;" : "=f"(lo), "=f"(hi) : "l"(a));
}

// ---------------- K1: x_src/x_dst projections + degree histogram -------------
__global__ void __launch_bounds__(512, 1) k_proj(
    const float* __restrict__ x,
    const float* __restrict__ Wsrc, const float* __restrict__ bsrc,
    const float* __restrict__ Wdst, const float* __restrict__ bdst,
    const int* __restrict__ dst, int n_nodes, int n_edges)
{
    extern __shared__ float sm[];
    float* Ws_s = sm;                 // 16384 floats
    float* Wd_s = sm + 16384;         // 16384 floats
    float* shx  = sm + 32768;         // [HID][TPAD] transposed x tile
    int tid = threadIdx.x;
    int tx = tid & 31;                // cols tx*4 .. tx*4+3
    int ty = tid >> 5;                // rows ty*4 .. ty*4+3
    int base = blockIdx.x * TM;

    const float4* Wsg = (const float4*)Wsrc;
    const float4* Wdg = (const float4*)Wdst;
    #pragma unroll
    for (int i = tid; i < 4096; i += 512) {
        ((float4*)Ws_s)[i] = __ldg(&Wsg[i]);
        ((float4*)Wd_s)[i] = __ldg(&Wdg[i]);
    }
    for (int i = tid; i < TM * 32; i += 512) {
        int r  = i >> 5;
        int c4 = (i & 31) * 4;
        int row = base + r;
        float4 v = make_float4(0.f, 0.f, 0.f, 0.f);
        if (row < n_nodes) v = *(const float4*)&x[(size_t)row * HID + c4];
        shx[(c4 + 0) * TPAD + r] = v.x; shx[(c4 + 1) * TPAD + r] = v.y;
        shx[(c4 + 2) * TPAD + r] = v.z; shx[(c4 + 3) * TPAD + r] = v.w;
    }
    __syncthreads();

    u64 as[2][4], ad[2][4];
    #pragma unroll
    for (int p = 0; p < 2; p++)
        #pragma unroll
        for (int c = 0; c < 4; c++) { as[p][c] = 0ull; ad[p][c] = 0ull; }

    int r0 = ty * 4;

    #pragma unroll 4
    for (int k = 0; k < HID; k++) {
        float4 ws = *(const float4*)&Ws_s[k * HID + tx * 4];
        float4 wd = *(const float4*)&Wd_s[k * HID + tx * 4];
        u64 x2[2];
        x2[0] = *(const u64*)&shx[k * TPAD + r0];
        x2[1] = *(const u64*)&shx[k * TPAD + r0 + 2];
        u64 s0 = pk2(ws.x, ws.x), s1 = pk2(ws.y, ws.y),
            s2 = pk2(ws.z, ws.z), s3 = pk2(ws.w, ws.w);
        u64 d0 = pk2(wd.x, wd.x), d1 = pk2(wd.y, wd.y),
            d2 = pk2(wd.z, wd.z), d3 = pk2(wd.w, wd.w);
        #pragma unroll
        for (int p = 0; p < 2; p++) {
            as[p][0] = fma2(x2[p], s0, as[p][0]);
            as[p][1] = fma2(x2[p], s1, as[p][1]);
            as[p][2] = fma2(x2[p], s2, as[p][2]);
            as[p][3] = fma2(x2[p], s3, as[p][3]);
            ad[p][0] = fma2(x2[p], d0, ad[p][0]);
            ad[p][1] = fma2(x2[p], d1, ad[p][1]);
            ad[p][2] = fma2(x2[p], d2, ad[p][2]);
            ad[p][3] = fma2(x2[p], d3, ad[p][3]);
        }
    }

    int col4 = tx * 4;
    float4 bs4 = __ldg(&((const float4*)bsrc)[tx]);
    float4 bd4 = __ldg(&((const float4*)bdst)[tx]);
    #pragma unroll
    for (int p = 0; p < 2; p++) {
        #pragma unroll
        for (int h = 0; h < 2; h++) {
            int row = base + r0 + 2 * p + h;
            if (row >= n_nodes) continue;
            float4 os, od; float lo, hi;
            unpk2(as[p][0], lo, hi); os.x = (h ? hi : lo) + bs4.x;
            unpk2(as[p][1], lo, hi); os.y = (h ? hi : lo) + bs4.y;
            unpk2(as[p][2], lo, hi); os.z = (h ? hi : lo) + bs4.z;
            unpk2(as[p][3], lo, hi); os.w = (h ? hi : lo) + bs4.w;
            unpk2(ad[p][0], lo, hi); od.x = (h ? hi : lo) + bd4.x;
            unpk2(ad[p][1], lo, hi); od.y = (h ? hi : lo) + bd4.y;
            unpk2(ad[p][2], lo, hi); od.z = (h ? hi : lo) + bd4.z;
            unpk2(ad[p][3], lo, hi); od.w = (h ? hi : lo) + bd4.w;
            *(float4*)&g_xsrc[(size_t)row * HID + col4] = os;
            *(float4*)&g_xdst[(size_t)row * HID + col4] = od;
        }
    }

    // degree histogram (independent of GEMM stores, grid-stride)
    for (int i = blockIdx.x * 512 + tid; i < n_edges; i += gridDim.x * 512)
        atomicAdd(&g_deg[__ldg(dst + i)], 1);
}

// ---------------- scan kernels for CSR offsets --------------------------------
__global__ void k_scan1(int n_nodes) {
    int idx = blockIdx.x * 1024 + threadIdx.x;
    int lane = threadIdx.x & 31, w = threadIdx.x >> 5;
    int v = (idx < n_nodes) ? g_deg[idx] : 0;
    int x = v;
    #pragma unroll
    for (int off = 1; off < 32; off <<= 1) {
        int y = __shfl_up_sync(0xffffffffu, x, off);
        if (lane >= off) x += y;
    }
    __shared__ int ws[32];
    if (lane == 31) ws[w] = x;
    __syncthreads();
    if (w == 0) {
        int s = ws[lane];
        #pragma unroll
        for (int off = 1; off < 32; off <<= 1) {
            int y = __shfl_up_sync(0xffffffffu, s, off);
            if (lane >= off) s += y;
        }
        ws[lane] = s;
    }
    __syncthreads();
    int incl = x + (w > 0 ? ws[w - 1] : 0);
    if (idx < n_nodes) g_off[idx + 1] = incl;
    if (threadIdx.x == 1023) g_part[blockIdx.x] = incl;
}

__global__ void k_scan2(int n_nodes) {
    int b = blockIdx.x;
    __shared__ int pre;
    if (threadIdx.x == 0) {
        int s = 0;
        for (int j = 0; j < b; j++) s += g_part[j];
        pre = s;
        if (b == 0) g_off[0] = 0;
    }
    __syncthreads();
    int idx = b * 1024 + threadIdx.x;
    if (idx < n_nodes) g_off[idx + 1] += pre;
}

// ---------------- scatter edges into CSR buckets -------------------------------
__global__ void k_scatter(const int* __restrict__ src, const int* __restrict__ dst,
                          const int* __restrict__ et, int n_edges)
{
    int e = blockIdx.x * blockDim.x + threadIdx.x;
    if (e >= n_edges) return;
    int d = __ldg(dst + e);
    int p = atomicAdd(&g_pos[d], 1);
    g_pk[g_off[d] + p] = __ldg(src + e) | (__ldg(et + e) << 20);
}

// ---------------- Kf: FiLM params -------------------------------------------
__global__ void k_film(const float* __restrict__ task,
                       const float* __restrict__ Wf,
                       const float* __restrict__ bf)
{
    int j = threadIdx.x;  // 256 threads
    float acc = bf[j];
    for (int k = 0; k < HID; k++)
        acc = fmaf(task[k], Wf[k * 2 * HID + j], acc);
    if (j < HID) g_gamma[j] = 1.0f + 0.5f * tanhf(acc);
    else         g_beta[j - HID] = acc;
}

// ---------------- K2: CSR edge pass, warp per dst node, 4-deep pipeline ------
__global__ void __launch_bounds__(256) k_edge(
    const float* __restrict__ edge_emb, const float* __restrict__ att,
    int n_nodes)
{
    int node = (blockIdx.x * blockDim.x + threadIdx.x) >> 5;
    int lane = threadIdx.x & 31;
    if (node >= n_nodes) return;

    float4 w  = __ldg(&((const float4*)att)[lane]);
    float4 xd = *(const float4*)&g_xdst[(size_t)node * HID + lane * 4];

    int beg = g_off[node], end = g_off[node + 1];
    const float4* xsg = (const float4*)g_xsrc;
    const float4* eeg = (const float4*)edge_emb;

    float4 acc = make_float4(0.f, 0.f, 0.f, 0.f);
    float  ssum = 0.0f;

    int e = beg;
    // main pipeline: 4 edges per iteration, all gathers issued up front
    for (; e + 4 <= end; e += 4) {
        int pk0 = __ldg(&g_pk[e + 0]);
        int pk1 = __ldg(&g_pk[e + 1]);
        int pk2_ = __ldg(&g_pk[e + 2]);
        int pk3 = __ldg(&g_pk[e + 3]);
        float4 a0 = __ldg(&xsg[(size_t)(pk0 & 0xFFFFF) * 32 + lane]);
        float4 a1 = __ldg(&xsg[(size_t)(pk1 & 0xFFFFF) * 32 + lane]);
        float4 a2 = __ldg(&xsg[(size_t)(pk2_ & 0xFFFFF) * 32 + lane]);
        float4 a3 = __ldg(&xsg[(size_t)(pk3 & 0xFFFFF) * 32 + lane]);
        float4 c0 = __ldg(&eeg[(pk0 >> 20) * 32 + lane]);
        float4 c1 = __ldg(&eeg[(pk1 >> 20) * 32 + lane]);
        float4 c2 = __ldg(&eeg[(pk2_ >> 20) * 32 + lane]);
        float4 c3 = __ldg(&eeg[(pk3 >> 20) * 32 + lane]);

        float t, p0, p1, p2, p3;
        t = a0.x + xd.x + c0.x; t = (t > 0.f) ? t : 0.2f * t; p0 = t * w.x;
        t = a0.y + xd.y + c0.y; t = (t > 0.f) ? t : 0.2f * t; p0 = fmaf(t, w.y, p0);
        t = a0.z + xd.z + c0.z; t = (t > 0.f) ? t : 0.2f * t; p0 = fmaf(t, w.z, p0);
        t = a0.w + xd.w + c0.w; t = (t > 0.f) ? t : 0.2f * t; p0 = fmaf(t, w.w, p0);
        t = a1.x + xd.x + c1.x; t = (t > 0.f) ? t : 0.2f * t; p1 = t * w.x;
        t = a1.y + xd.y + c1.y; t = (t > 0.f) ? t : 0.2f * t; p1 = fmaf(t, w.y, p1);
        t = a1.z + xd.z + c1.z; t = (t > 0.f) ? t : 0.2f * t; p1 = fmaf(t, w.z, p1);
        t = a1.w + xd.w + c1.w; t = (t > 0.f) ? t : 0.2f * t; p1 = fmaf(t, w.w, p1);
        t = a2.x + xd.x + c2.x; t = (t > 0.f) ? t : 0.2f * t; p2 = t * w.x;
        t = a2.y + xd.y + c2.y; t = (t > 0.f) ? t : 0.2f * t; p2 = fmaf(t, w.y, p2);
        t = a2.z + xd.z + c2.z; t = (t > 0.f) ? t : 0.2f * t; p2 = fmaf(t, w.z, p2);
        t = a2.w + xd.w + c2.w; t = (t > 0.f) ? t : 0.2f * t; p2 = fmaf(t, w.w, p2);
        t = a3.x + xd.x + c3.x; t = (t > 0.f) ? t : 0.2f * t; p3 = t * w.x;
        t = a3.y + xd.y + c3.y; t = (t > 0.f) ? t : 0.2f * t; p3 = fmaf(t, w.y, p3);
        t = a3.z + xd.z + c3.z; t = (t > 0.f) ? t : 0.2f * t; p3 = fmaf(t, w.z, p3);
        t = a3.w + xd.w + c3.w; t = (t > 0.f) ? t : 0.2f * t; p3 = fmaf(t, w.w, p3);

        #pragma unroll
        for (int off = 4; off; off >>= 1) {
            p0 += __shfl_xor_sync(0xffffffffu, p0, off);
            p1 += __shfl_xor_sync(0xffffffffu, p1, off);
            p2 += __shfl_xor_sync(0xffffffffu, p2, off);
            p3 += __shfl_xor_sync(0xffffffffu, p3, off);
        }
        float ex0 = __expf(p0), ex1 = __expf(p1);
        float ex2 = __expf(p2), ex3 = __expf(p3);
        ssum += (ex0 + ex1) + (ex2 + ex3);
        acc.x = fmaf(a0.x, ex0, fmaf(a1.x, ex1, fmaf(a2.x, ex2, fmaf(a3.x, ex3, acc.x))));
        acc.y = fmaf(a0.y, ex0, fmaf(a1.y, ex1, fmaf(a2.y, ex2, fmaf(a3.y, ex3, acc.y))));
        acc.z = fmaf(a0.z, ex0, fmaf(a1.z, ex1, fmaf(a2.z, ex2, fmaf(a3.z, ex3, acc.z))));
        acc.w = fmaf(a0.w, ex0, fmaf(a1.w, ex1, fmaf(a2.w, ex2, fmaf(a3.w, ex3, acc.w))));
    }
    // remainder
    for (; e < end; e++) {
        int pk = __ldg(&g_pk[e]);
        float4 a = __ldg(&xsg[(size_t)(pk & 0xFFFFF) * 32 + lane]);
        float4 c = __ldg(&eeg[(pk >> 20) * 32 + lane]);
        float t, p;
        t = a.x + xd.x + c.x; t = (t > 0.f) ? t : 0.2f * t; p = t * w.x;
        t = a.y + xd.y + c.y; t = (t > 0.f) ? t : 0.2f * t; p = fmaf(t, w.y, p);
        t = a.z + xd.z + c.z; t = (t > 0.f) ? t : 0.2f * t; p = fmaf(t, w.z, p);
        t = a.w + xd.w + c.w; t = (t > 0.f) ? t : 0.2f * t; p = fmaf(t, w.w, p);
        p += __shfl_xor_sync(0xffffffffu, p, 4);
        p += __shfl_xor_sync(0xffffffffu, p, 2);
        p += __shfl_xor_sync(0xffffffffu, p, 1);
        float ex = __expf(p);
        ssum += ex;
        acc.x = fmaf(a.x, ex, acc.x);
        acc.y = fmaf(a.y, ex, acc.y);
        acc.z = fmaf(a.z, ex, acc.z);
        acc.w = fmaf(a.w, ex, acc.w);
    }

    float inv = 1.0f / fmaxf(ssum, 1e-12f);
    float4 o;
    o.x = acc.x * inv; o.y = acc.y * inv;
    o.z = acc.z * inv; o.w = acc.w * inv;
    *(float4*)&g_agg[(size_t)node * HID + lane * 4] = o;
}

// ---------------- K5: out = LN(node + FiLM(agg@W_out+b)) ---------------------
__global__ void __launch_bounds__(512, 2) k_out(
    const float* __restrict__ node,
    const float* __restrict__ Wout, const float* __restrict__ bout,
    const float* __restrict__ normw, const float* __restrict__ normb,
    float* __restrict__ out, int n_nodes)
{
    extern __shared__ float sm[];
    float* W_s = sm;                  // 16384 floats
    float* shx = sm + 16384;          // [HID][TPAD] transposed tile
    int tid = threadIdx.x;
    int tx = tid & 31;
    int ty = tid >> 5;                // 0..15
    int base = blockIdx.x * TM;

    const float4* Wg = (const float4*)Wout;
    #pragma unroll
    for (int i = tid; i < 4096; i += 512)
        ((float4*)W_s)[i] = __ldg(&Wg[i]);

    for (int i = tid; i < TM * 32; i += 512) {
        int r  = i >> 5;
        int c4 = (i & 31) * 4;
        int row = base + r;
        float4 v = make_float4(0.f, 0.f, 0.f, 0.f);
        if (row < n_nodes) v = *(const float4*)&g_agg[(size_t)row * HID + c4];
        shx[(c4 + 0) * TPAD + r] = v.x; shx[(c4 + 1) * TPAD + r] = v.y;
        shx[(c4 + 2) * TPAD + r] = v.z; shx[(c4 + 3) * TPAD + r] = v.w;
    }
    __syncthreads();

    u64 acc[2][4];
    #pragma unroll
    for (int p = 0; p < 2; p++)
        #pragma unroll
        for (int c = 0; c < 4; c++) acc[p][c] = 0ull;

    int r0 = ty * 4;

    #pragma unroll 4
    for (int k = 0; k < HID; k++) {
        float4 w = *(const float4*)&W_s[k * HID + tx * 4];
        u64 x2[2];
        x2[0] = *(const u64*)&shx[k * TPAD + r0];
        x2[1] = *(const u64*)&shx[k * TPAD + r0 + 2];
        u64 w0 = pk2(w.x, w.x), w1 = pk2(w.y, w.y),
            w2 = pk2(w.z, w.z), w3 = pk2(w.w, w.w);
        #pragma unroll
        for (int p = 0; p < 2; p++) {
            acc[p][0] = fma2(x2[p], w0, acc[p][0]);
            acc[p][1] = fma2(x2[p], w1, acc[p][1]);
            acc[p][2] = fma2(x2[p], w2, acc[p][2]);
            acc[p][3] = fma2(x2[p], w3, acc[p][3]);
        }
    }

    // epilogue: FiLM + residual + LayerNorm, all within the warp
    int col4 = tx * 4;
    float4 bo4 = __ldg(&((const float4*)bout)[tx]);
    float4 gm4 = *(const float4*)&g_gamma[col4];
    float4 bt4 = *(const float4*)&g_beta[col4];
    float4 nw4 = __ldg(&((const float4*)normw)[tx]);
    float4 nb4 = __ldg(&((const float4*)normb)[tx]);

    #pragma unroll
    for (int p = 0; p < 2; p++) {
        #pragma unroll
        for (int h = 0; h < 2; h++) {
            int row = base + r0 + 2 * p + h;
            bool ok = (row < n_nodes);
            float4 nd = make_float4(0.f, 0.f, 0.f, 0.f);
            if (ok) nd = *(const float4*)&node[(size_t)row * HID + col4];
            float lo, hi, y0, y1, y2, y3;
            unpk2(acc[p][0], lo, hi); y0 = nd.x + ((h ? hi : lo) + bo4.x) * gm4.x + bt4.x;
            unpk2(acc[p][1], lo, hi); y1 = nd.y + ((h ? hi : lo) + bo4.y) * gm4.y + bt4.y;
            unpk2(acc[p][2], lo, hi); y2 = nd.z + ((h ? hi : lo) + bo4.z) * gm4.z + bt4.z;
            unpk2(acc[p][3], lo, hi); y3 = nd.w + ((h ? hi : lo) + bo4.w) * gm4.w + bt4.w;

            float s1 = y0 + y1 + y2 + y3;
            float s2 = y0 * y0 + y1 * y1 + y2 * y2 + y3 * y3;
            #pragma unroll
            for (int off = 16; off; off >>= 1) {
                s1 += __shfl_xor_sync(0xffffffffu, s1, off);
                s2 += __shfl_xor_sync(0xffffffffu, s2, off);
            }
            float mu  = s1 * (1.0f / HID);
            float var = s2 * (1.0f / HID) - mu * mu;
            float inv = rsqrtf(var + 1e-5f);
            if (ok) {
                float4 o;
                o.x = (y0 - mu) * inv * nw4.x + nb4.x;
                o.y = (y1 - mu) * inv * nw4.y + nb4.y;
                o.z = (y2 - mu) * inv * nw4.z + nb4.z;
                o.w = (y3 - mu) * inv * nw4.w + nb4.w;
                *(float4*)&out[(size_t)row * HID + col4] = o;
            }
        }
    }
}

// ---------------- launch -----------------------------------------------------
extern "C" void kernel_launch(void* const* d_in, const int* in_sizes, int n_in,
                              void* d_out, int out_size)
{
    const float* node   = (const float*)d_in[0];
    const int*   eidx   = (const int*)  d_in[1];
    const int*   etype  = (const int*)  d_in[2];
    const float* task   = (const float*)d_in[3];
    const float* Wsrc   = (const float*)d_in[4];
    const float* bsrc   = (const float*)d_in[5];
    const float* Wdst   = (const float*)d_in[6];
    const float* bdst   = (const float*)d_in[7];
    const float* eemb   = (const float*)d_in[8];
    const float* att    = (const float*)d_in[9];
    const float* Wout   = (const float*)d_in[10];
    const float* bout   = (const float*)d_in[11];
    const float* normw  = (const float*)d_in[12];
    const float* normb  = (const float*)d_in[13];
    const float* Wfilm  = (const float*)d_in[14];
    const float* bfilm  = (const float*)d_in[15];
    float* out = (float*)d_out;

    int n_nodes = in_sizes[0] / HID;
    int n_edges = in_sizes[2];
    const int* src = eidx;
    const int* dst = eidx + n_edges;

    void* p_deg = nullptr; void* p_pos = nullptr;
    cudaGetSymbolAddress(&p_deg, g_deg);
    cudaGetSymbolAddress(&p_pos, g_pos);
    cudaMemsetAsync(p_deg, 0, (size_t)n_nodes * sizeof(int));
    cudaMemsetAsync(p_pos, 0, (size_t)n_nodes * sizeof(int));

    const int smem_proj = (2 * 16384 + HID * TPAD) * sizeof(float);  // ~164KB
    const int smem_out  = (16384 + HID * TPAD) * sizeof(float);      // ~99KB
    cudaFuncSetAttribute(k_proj, cudaFuncAttributeMaxDynamicSharedMemorySize, smem_proj);
    cudaFuncSetAttribute(k_out,  cudaFuncAttributeMaxDynamicSharedMemorySize, smem_out);

    int gblk = (n_nodes + TM - 1) / TM;
    int nsb  = (n_nodes + 1023) / 1024;

    k_proj<<<gblk, 512, smem_proj>>>(node, Wsrc, bsrc, Wdst, bdst, dst,
                                     n_nodes, n_edges);
    k_scan1<<<nsb, 1024>>>(n_nodes);
    k_scan2<<<nsb, 1024>>>(n_nodes);
    k_scatter<<<(n_edges + 255) / 256, 256>>>(src, dst, etype, n_edges);
    k_film<<<1, 2 * HID>>>(task, Wfilm, bfilm);
    k_edge<<<(n_nodes * 32 + 255) / 256, 256>>>(eemb, att, n_nodes);
    k_out<<<gblk, 512, smem_out>>>(node, Wout, bout, normw, normb, out, n_nodes);
}

// round 7
// speedup vs baseline: 1.0708x; 1.0652x over previous
#include <cuda_runtime.h>
#include <math.h>

#define N_NODES 50000
#define N_EDGES 500000
#define HID 128
#define NHEAD 4
#define TM 128           // rows per block in GEMM kernels
#define TPADP 132        // padded row length (floats) for transposed tile; mult of 4

typedef unsigned long long u64;

// ---------------- scratch (device globals; no allocations allowed) ----------
__device__ float g_xsrc[N_NODES * HID];
__device__ float g_xdst[N_NODES * HID];
__device__ float g_agg[N_NODES * HID];     // NORMALIZED aggregated messages
__device__ float g_gamma[HID];             // 1 + 0.5*tanh(gamma)
__device__ float g_beta[HID];
__device__ int   g_deg[N_NODES];           // degree histogram
__device__ int   g_pos[N_NODES];           // scatter cursors
__device__ int   g_off[N_NODES + 1];       // CSR offsets
__device__ int   g_pk[N_EDGES];            // packed (etype<<20)|src per edge
__device__ int   g_part[64];               // scan partials

// ---------------- f32x2 helpers ----------------------------------------------
__device__ __forceinline__ u64 pk2(float lo, float hi) {
    u64 r;
    asm("mov.b64 %0, {%1, %2};" : "=l"(r) : "f"(lo), "f"(hi));
    return r;
}
__device__ __forceinline__ u64 fma2(u64 a, u64 b, u64 c) {
    u64 d;
    asm("fma.rn.f32x2 %0, %1, %2, %3;" : "=l"(d) : "l"(a), "l"(b), "l"(c));
    return d;
}
__device__ __forceinline__ void unpk2(u64 a, float& lo, float& hi) {
    asm("mov.b64 {%0, %1}, %2;" : "=f"(lo), "=f"(hi) : "l"(a));
}

// ---------------- K1: x_src/x_dst projections + degree histogram -------------
// 512 threads, 8 rows x 4 cols per thread, TM=128.
// smem: Ws(64K)+Wd(64K)+tile(66K) = ~194KB -> 1 CTA/SM, 16 warps.
__global__ void __launch_bounds__(512, 1) k_proj(
    const float* __restrict__ x,
    const float* __restrict__ Wsrc, const float* __restrict__ bsrc,
    const float* __restrict__ Wdst, const float* __restrict__ bdst,
    const int* __restrict__ dst, int n_nodes, int n_edges)
{
    extern __shared__ float sm[];
    float* Ws_s = sm;                 // 16384 floats
    float* Wd_s = sm + 16384;         // 16384 floats
    float* shx  = sm + 32768;         // [HID][TPADP] transposed x tile
    int tid = threadIdx.x;
    int tx = tid & 31;                // cols tx*4 .. tx*4+3
    int ty = tid >> 5;                // rows ty*8 .. ty*8+7
    int base = blockIdx.x * TM;
    int tx4 = tx * 4;

    const float4* Wsg = (const float4*)Wsrc;
    const float4* Wdg = (const float4*)Wdst;
    #pragma unroll
    for (int i = tid; i < 4096; i += 512) {
        ((float4*)Ws_s)[i] = __ldg(&Wsg[i]);
        ((float4*)Wd_s)[i] = __ldg(&Wdg[i]);
    }
    // load + transpose input tile (128 rows x 32 float4-groups)
    for (int i = tid; i < TM * 32; i += 512) {
        int r  = i >> 5;
        int c4 = (i & 31) * 4;
        int row = base + r;
        float4 v = make_float4(0.f, 0.f, 0.f, 0.f);
        if (row < n_nodes) v = *(const float4*)&x[(size_t)row * HID + c4];
        shx[(c4 + 0) * TPADP + r] = v.x; shx[(c4 + 1) * TPADP + r] = v.y;
        shx[(c4 + 2) * TPADP + r] = v.z; shx[(c4 + 3) * TPADP + r] = v.w;
    }
    __syncthreads();

    u64 as[4][4], ad[4][4];
    #pragma unroll
    for (int p = 0; p < 4; p++)
        #pragma unroll
        for (int c = 0; c < 4; c++) { as[p][c] = 0ull; ad[p][c] = 0ull; }

    int r0 = ty * 8;

    #pragma unroll 4
    for (int k = 0; k < HID; k++) {
        float4 ws = *(const float4*)&Ws_s[k * HID + tx4];
        float4 wd = *(const float4*)&Wd_s[k * HID + tx4];
        // 8 rows = 4 row-pairs, loaded as two LDS.128 broadcasts, no movs
        ulonglong2 xv0 = *(const ulonglong2*)&shx[k * TPADP + r0];
        ulonglong2 xv1 = *(const ulonglong2*)&shx[k * TPADP + r0 + 4];
        u64 x2[4];
        x2[0] = xv0.x; x2[1] = xv0.y; x2[2] = xv1.x; x2[3] = xv1.y;
        u64 s0 = pk2(ws.x, ws.x), s1 = pk2(ws.y, ws.y),
            s2 = pk2(ws.z, ws.z), s3 = pk2(ws.w, ws.w);
        u64 d0 = pk2(wd.x, wd.x), d1 = pk2(wd.y, wd.y),
            d2 = pk2(wd.z, wd.z), d3 = pk2(wd.w, wd.w);
        #pragma unroll
        for (int p = 0; p < 4; p++) {
            as[p][0] = fma2(x2[p], s0, as[p][0]);
            as[p][1] = fma2(x2[p], s1, as[p][1]);
            as[p][2] = fma2(x2[p], s2, as[p][2]);
            as[p][3] = fma2(x2[p], s3, as[p][3]);
            ad[p][0] = fma2(x2[p], d0, ad[p][0]);
            ad[p][1] = fma2(x2[p], d1, ad[p][1]);
            ad[p][2] = fma2(x2[p], d2, ad[p][2]);
            ad[p][3] = fma2(x2[p], d3, ad[p][3]);
        }
    }

    float4 bs4 = __ldg(&((const float4*)bsrc)[tx]);
    float4 bd4 = __ldg(&((const float4*)bdst)[tx]);
    #pragma unroll
    for (int p = 0; p < 4; p++) {
        #pragma unroll
        for (int h = 0; h < 2; h++) {
            int row = base + r0 + 2 * p + h;
            if (row >= n_nodes) continue;
            float4 os, od; float lo, hi;
            unpk2(as[p][0], lo, hi); os.x = (h ? hi : lo) + bs4.x;
            unpk2(as[p][1], lo, hi); os.y = (h ? hi : lo) + bs4.y;
            unpk2(as[p][2], lo, hi); os.z = (h ? hi : lo) + bs4.z;
            unpk2(as[p][3], lo, hi); os.w = (h ? hi : lo) + bs4.w;
            unpk2(ad[p][0], lo, hi); od.x = (h ? hi : lo) + bd4.x;
            unpk2(ad[p][1], lo, hi); od.y = (h ? hi : lo) + bd4.y;
            unpk2(ad[p][2], lo, hi); od.z = (h ? hi : lo) + bd4.z;
            unpk2(ad[p][3], lo, hi); od.w = (h ? hi : lo) + bd4.w;
            *(float4*)&g_xsrc[(size_t)row * HID + tx4] = os;
            *(float4*)&g_xdst[(size_t)row * HID + tx4] = od;
        }
    }

    // degree histogram (grid-stride)
    for (int i = blockIdx.x * 512 + tid; i < n_edges; i += gridDim.x * 512)
        atomicAdd(&g_deg[__ldg(dst + i)], 1);
}

// ---------------- scan kernels for CSR offsets --------------------------------
__global__ void k_scan1(int n_nodes) {
    int idx = blockIdx.x * 1024 + threadIdx.x;
    int lane = threadIdx.x & 31, w = threadIdx.x >> 5;
    int v = (idx < n_nodes) ? g_deg[idx] : 0;
    if (idx < n_nodes) g_pos[idx] = 0;   // fold cursor zeroing in here
    int x = v;
    #pragma unroll
    for (int off = 1; off < 32; off <<= 1) {
        int y = __shfl_up_sync(0xffffffffu, x, off);
        if (lane >= off) x += y;
    }
    __shared__ int ws[32];
    if (lane == 31) ws[w] = x;
    __syncthreads();
    if (w == 0) {
        int s = ws[lane];
        #pragma unroll
        for (int off = 1; off < 32; off <<= 1) {
            int y = __shfl_up_sync(0xffffffffu, s, off);
            if (lane >= off) s += y;
        }
        ws[lane] = s;
    }
    __syncthreads();
    int incl = x + (w > 0 ? ws[w - 1] : 0);
    if (idx < n_nodes) g_off[idx + 1] = incl;
    if (threadIdx.x == 1023) g_part[blockIdx.x] = incl;
}

__global__ void k_scan2(int n_nodes) {
    int b = blockIdx.x;
    __shared__ int pre;
    if (threadIdx.x == 0) {
        int s = 0;
        for (int j = 0; j < b; j++) s += g_part[j];
        pre = s;
        if (b == 0) g_off[0] = 0;
    }
    __syncthreads();
    int idx = b * 1024 + threadIdx.x;
    if (idx < n_nodes) g_off[idx + 1] += pre;
}

// ---------------- scatter edges into CSR buckets -------------------------------
__global__ void k_scatter(const int* __restrict__ src, const int* __restrict__ dst,
                          const int* __restrict__ et, int n_edges)
{
    int e = blockIdx.x * blockDim.x + threadIdx.x;
    if (e >= n_edges) return;
    int d = __ldg(dst + e);
    int p = atomicAdd(&g_pos[d], 1);
    g_pk[g_off[d] + p] = __ldg(src + e) | (__ldg(et + e) << 20);
}

// ---------------- Kf: FiLM params -------------------------------------------
__global__ void k_film(const float* __restrict__ task,
                       const float* __restrict__ Wf,
                       const float* __restrict__ bf)
{
    int j = threadIdx.x;  // 256 threads
    float acc = bf[j];
    for (int k = 0; k < HID; k++)
        acc = fmaf(task[k], Wf[k * 2 * HID + j], acc);
    if (j < HID) g_gamma[j] = 1.0f + 0.5f * tanhf(acc);
    else         g_beta[j - HID] = acc;
}

// ---------------- K2: CSR edge pass, warp per dst node, 4-deep pipeline ------
__global__ void __launch_bounds__(256) k_edge(
    const float* __restrict__ edge_emb, const float* __restrict__ att,
    int n_nodes)
{
    int node = (blockIdx.x * blockDim.x + threadIdx.x) >> 5;
    int lane = threadIdx.x & 31;
    if (node >= n_nodes) return;

    float4 w  = __ldg(&((const float4*)att)[lane]);
    float4 xd = *(const float4*)&g_xdst[(size_t)node * HID + lane * 4];

    int beg = g_off[node], end = g_off[node + 1];
    const float4* xsg = (const float4*)g_xsrc;
    const float4* eeg = (const float4*)edge_emb;

    float4 acc = make_float4(0.f, 0.f, 0.f, 0.f);
    float  ssum = 0.0f;

    int e = beg;
    for (; e + 4 <= end; e += 4) {
        int pk0 = __ldg(&g_pk[e + 0]);
        int pk1 = __ldg(&g_pk[e + 1]);
        int pk2_ = __ldg(&g_pk[e + 2]);
        int pk3 = __ldg(&g_pk[e + 3]);
        float4 a0 = __ldg(&xsg[(size_t)(pk0 & 0xFFFFF) * 32 + lane]);
        float4 a1 = __ldg(&xsg[(size_t)(pk1 & 0xFFFFF) * 32 + lane]);
        float4 a2 = __ldg(&xsg[(size_t)(pk2_ & 0xFFFFF) * 32 + lane]);
        float4 a3 = __ldg(&xsg[(size_t)(pk3 & 0xFFFFF) * 32 + lane]);
        float4 c0 = __ldg(&eeg[(pk0 >> 20) * 32 + lane]);
        float4 c1 = __ldg(&eeg[(pk1 >> 20) * 32 + lane]);
        float4 c2 = __ldg(&eeg[(pk2_ >> 20) * 32 + lane]);
        float4 c3 = __ldg(&eeg[(pk3 >> 20) * 32 + lane]);

        float t, p0, p1, p2, p3;
        t = a0.x + xd.x + c0.x; t = (t > 0.f) ? t : 0.2f * t; p0 = t * w.x;
        t = a0.y + xd.y + c0.y; t = (t > 0.f) ? t : 0.2f * t; p0 = fmaf(t, w.y, p0);
        t = a0.z + xd.z + c0.z; t = (t > 0.f) ? t : 0.2f * t; p0 = fmaf(t, w.z, p0);
        t = a0.w + xd.w + c0.w; t = (t > 0.f) ? t : 0.2f * t; p0 = fmaf(t, w.w, p0);
        t = a1.x + xd.x + c1.x; t = (t > 0.f) ? t : 0.2f * t; p1 = t * w.x;
        t = a1.y + xd.y + c1.y; t = (t > 0.f) ? t : 0.2f * t; p1 = fmaf(t, w.y, p1);
        t = a1.z + xd.z + c1.z; t = (t > 0.f) ? t : 0.2f * t; p1 = fmaf(t, w.z, p1);
        t = a1.w + xd.w + c1.w; t = (t > 0.f) ? t : 0.2f * t; p1 = fmaf(t, w.w, p1);
        t = a2.x + xd.x + c2.x; t = (t > 0.f) ? t : 0.2f * t; p2 = t * w.x;
        t = a2.y + xd.y + c2.y; t = (t > 0.f) ? t : 0.2f * t; p2 = fmaf(t, w.y, p2);
        t = a2.z + xd.z + c2.z; t = (t > 0.f) ? t : 0.2f * t; p2 = fmaf(t, w.z, p2);
        t = a2.w + xd.w + c2.w; t = (t > 0.f) ? t : 0.2f * t; p2 = fmaf(t, w.w, p2);
        t = a3.x + xd.x + c3.x; t = (t > 0.f) ? t : 0.2f * t; p3 = t * w.x;
        t = a3.y + xd.y + c3.y; t = (t > 0.f) ? t : 0.2f * t; p3 = fmaf(t, w.y, p3);
        t = a3.z + xd.z + c3.z; t = (t > 0.f) ? t : 0.2f * t; p3 = fmaf(t, w.z, p3);
        t = a3.w + xd.w + c3.w; t = (t > 0.f) ? t : 0.2f * t; p3 = fmaf(t, w.w, p3);

        #pragma unroll
        for (int off = 4; off; off >>= 1) {
            p0 += __shfl_xor_sync(0xffffffffu, p0, off);
            p1 += __shfl_xor_sync(0xffffffffu, p1, off);
            p2 += __shfl_xor_sync(0xffffffffu, p2, off);
            p3 += __shfl_xor_sync(0xffffffffu, p3, off);
        }
        float ex0 = __expf(p0), ex1 = __expf(p1);
        float ex2 = __expf(p2), ex3 = __expf(p3);
        ssum += (ex0 + ex1) + (ex2 + ex3);
        acc.x = fmaf(a0.x, ex0, fmaf(a1.x, ex1, fmaf(a2.x, ex2, fmaf(a3.x, ex3, acc.x))));
        acc.y = fmaf(a0.y, ex0, fmaf(a1.y, ex1, fmaf(a2.y, ex2, fmaf(a3.y, ex3, acc.y))));
        acc.z = fmaf(a0.z, ex0, fmaf(a1.z, ex1, fmaf(a2.z, ex2, fmaf(a3.z, ex3, acc.z))));
        acc.w = fmaf(a0.w, ex0, fmaf(a1.w, ex1, fmaf(a2.w, ex2, fmaf(a3.w, ex3, acc.w))));
    }
    for (; e < end; e++) {
        int pk = __ldg(&g_pk[e]);
        float4 a = __ldg(&xsg[(size_t)(pk & 0xFFFFF) * 32 + lane]);
        float4 c = __ldg(&eeg[(pk >> 20) * 32 + lane]);
        float t, p;
        t = a.x + xd.x + c.x; t = (t > 0.f) ? t : 0.2f * t; p = t * w.x;
        t = a.y + xd.y + c.y; t = (t > 0.f) ? t : 0.2f * t; p = fmaf(t, w.y, p);
        t = a.z + xd.z + c.z; t = (t > 0.f) ? t : 0.2f * t; p = fmaf(t, w.z, p);
        t = a.w + xd.w + c.w; t = (t > 0.f) ? t : 0.2f * t; p = fmaf(t, w.w, p);
        p += __shfl_xor_sync(0xffffffffu, p, 4);
        p += __shfl_xor_sync(0xffffffffu, p, 2);
        p += __shfl_xor_sync(0xffffffffu, p, 1);
        float ex = __expf(p);
        ssum += ex;
        acc.x = fmaf(a.x, ex, acc.x);
        acc.y = fmaf(a.y, ex, acc.y);
        acc.z = fmaf(a.z, ex, acc.z);
        acc.w = fmaf(a.w, ex, acc.w);
    }

    float inv = 1.0f / fmaxf(ssum, 1e-12f);
    float4 o;
    o.x = acc.x * inv; o.y = acc.y * inv;
    o.z = acc.z * inv; o.w = acc.w * inv;
    *(float4*)&g_agg[(size_t)node * HID + lane * 4] = o;
}

// ---------------- K5: out = LN(node + FiLM(agg@W_out+b)) ---------------------
// 512 threads, 8 rows x 4 cols per thread, TM=128.
// smem: W(64K)+tile(66K) = ~130KB -> 1 CTA/SM, 16 warps.
__global__ void __launch_bounds__(512, 1) k_out(
    const float* __restrict__ node,
    const float* __restrict__ Wout, const float* __restrict__ bout,
    const float* __restrict__ normw, const float* __restrict__ normb,
    float* __restrict__ out, int n_nodes)
{
    extern __shared__ float sm[];
    float* W_s = sm;                  // 16384 floats
    float* shx = sm + 16384;          // [HID][TPADP] transposed tile
    int tid = threadIdx.x;
    int tx = tid & 31;
    int ty = tid >> 5;
    int base = blockIdx.x * TM;
    int tx4 = tx * 4;

    const float4* Wg = (const float4*)Wout;
    #pragma unroll
    for (int i = tid; i < 4096; i += 512)
        ((float4*)W_s)[i] = __ldg(&Wg[i]);

    for (int i = tid; i < TM * 32; i += 512) {
        int r  = i >> 5;
        int c4 = (i & 31) * 4;
        int row = base + r;
        float4 v = make_float4(0.f, 0.f, 0.f, 0.f);
        if (row < n_nodes) v = *(const float4*)&g_agg[(size_t)row * HID + c4];
        shx[(c4 + 0) * TPADP + r] = v.x; shx[(c4 + 1) * TPADP + r] = v.y;
        shx[(c4 + 2) * TPADP + r] = v.z; shx[(c4 + 3) * TPADP + r] = v.w;
    }
    __syncthreads();

    u64 acc[4][4];
    #pragma unroll
    for (int p = 0; p < 4; p++)
        #pragma unroll
        for (int c = 0; c < 4; c++) acc[p][c] = 0ull;

    int r0 = ty * 8;

    #pragma unroll 8
    for (int k = 0; k < HID; k++) {
        float4 w = *(const float4*)&W_s[k * HID + tx4];
        ulonglong2 xv0 = *(const ulonglong2*)&shx[k * TPADP + r0];
        ulonglong2 xv1 = *(const ulonglong2*)&shx[k * TPADP + r0 + 4];
        u64 x2[4];
        x2[0] = xv0.x; x2[1] = xv0.y; x2[2] = xv1.x; x2[3] = xv1.y;
        u64 w0 = pk2(w.x, w.x), w1 = pk2(w.y, w.y),
            w2 = pk2(w.z, w.z), w3 = pk2(w.w, w.w);
        #pragma unroll
        for (int p = 0; p < 4; p++) {
            acc[p][0] = fma2(x2[p], w0, acc[p][0]);
            acc[p][1] = fma2(x2[p], w1, acc[p][1]);
            acc[p][2] = fma2(x2[p], w2, acc[p][2]);
            acc[p][3] = fma2(x2[p], w3, acc[p][3]);
        }
    }

    // epilogue: FiLM + residual + LayerNorm, all within the warp
    float4 bo4 = __ldg(&((const float4*)bout)[tx]);
    float4 gm4 = *(const float4*)&g_gamma[tx4];
    float4 bt4 = *(const float4*)&g_beta[tx4];
    float4 nw4 = __ldg(&((const float4*)normw)[tx]);
    float4 nb4 = __ldg(&((const float4*)normb)[tx]);

    #pragma unroll
    for (int p = 0; p < 4; p++) {
        #pragma unroll
        for (int h = 0; h < 2; h++) {
            int row = base + r0 + 2 * p + h;
            bool ok = (row < n_nodes);
            float4 nd = make_float4(0.f, 0.f, 0.f, 0.f);
            if (ok) nd = *(const float4*)&node[(size_t)row * HID + tx4];
            float lo, hi, y0, y1, y2, y3;
            unpk2(acc[p][0], lo, hi); y0 = nd.x + ((h ? hi : lo) + bo4.x) * gm4.x + bt4.x;
            unpk2(acc[p][1], lo, hi); y1 = nd.y + ((h ? hi : lo) + bo4.y) * gm4.y + bt4.y;
            unpk2(acc[p][2], lo, hi); y2 = nd.z + ((h ? hi : lo) + bo4.z) * gm4.z + bt4.z;
            unpk2(acc[p][3], lo, hi); y3 = nd.w + ((h ? hi : lo) + bo4.w) * gm4.w + bt4.w;

            float s1 = y0 + y1 + y2 + y3;
            float s2 = y0 * y0 + y1 * y1 + y2 * y2 + y3 * y3;
            #pragma unroll
            for (int off = 16; off; off >>= 1) {
                s1 += __shfl_xor_sync(0xffffffffu, s1, off);
                s2 += __shfl_xor_sync(0xffffffffu, s2, off);
            }
            float mu  = s1 * (1.0f / HID);
            float var = s2 * (1.0f / HID) - mu * mu;
            float inv = rsqrtf(var + 1e-5f);
            if (ok) {
                float4 o;
                o.x = (y0 - mu) * inv * nw4.x + nb4.x;
                o.y = (y1 - mu) * inv * nw4.y + nb4.y;
                o.z = (y2 - mu) * inv * nw4.z + nb4.z;
                o.w = (y3 - mu) * inv * nw4.w + nb4.w;
                *(float4*)&out[(size_t)row * HID + tx4] = o;
            }
        }
    }
}

// ---------------- launch -----------------------------------------------------
extern "C" void kernel_launch(void* const* d_in, const int* in_sizes, int n_in,
                              void* d_out, int out_size)
{
    const float* node   = (const float*)d_in[0];
    const int*   eidx   = (const int*)  d_in[1];
    const int*   etype  = (const int*)  d_in[2];
    const float* task   = (const float*)d_in[3];
    const float* Wsrc   = (const float*)d_in[4];
    const float* bsrc   = (const float*)d_in[5];
    const float* Wdst   = (const float*)d_in[6];
    const float* bdst   = (const float*)d_in[7];
    const float* eemb   = (const float*)d_in[8];
    const float* att    = (const float*)d_in[9];
    const float* Wout   = (const float*)d_in[10];
    const float* bout   = (const float*)d_in[11];
    const float* normw  = (const float*)d_in[12];
    const float* normb  = (const float*)d_in[13];
    const float* Wfilm  = (const float*)d_in[14];
    const float* bfilm  = (const float*)d_in[15];
    float* out = (float*)d_out;

    int n_nodes = in_sizes[0] / HID;
    int n_edges = in_sizes[2];
    const int* src = eidx;
    const int* dst = eidx + n_edges;

    void* p_deg = nullptr;
    cudaGetSymbolAddress(&p_deg, g_deg);
    cudaMemsetAsync(p_deg, 0, (size_t)n_nodes * sizeof(int));

    const int smem_proj = (2 * 16384 + HID * TPADP) * sizeof(float);  // ~198KB
    const int smem_out  = (16384 + HID * TPADP) * sizeof(float);      // ~133KB
    cudaFuncSetAttribute(k_proj, cudaFuncAttributeMaxDynamicSharedMemorySize, smem_proj);
    cudaFuncSetAttribute(k_out,  cudaFuncAttributeMaxDynamicSharedMemorySize, smem_out);

    int gblk = (n_nodes + TM - 1) / TM;
    int nsb  = (n_nodes + 1023) / 1024;

    k_proj<<<gblk, 512, smem_proj>>>(node, Wsrc, bsrc, Wdst, bdst, dst,
                                     n_nodes, n_edges);
    k_scan1<<<nsb, 1024>>>(n_nodes);
    k_scan2<<<nsb, 1024>>>(n_nodes);
    k_scatter<<<(n_edges + 255) / 256, 256>>>(src, dst, etype, n_edges);
    k_film<<<1, 2 * HID>>>(task, Wfilm, bfilm);
    k_edge<<<(n_nodes * 32 + 255) / 256, 256>>>(eemb, att, n_nodes);
    k_out<<<gblk, 512, smem_out>>>(node, Wout, bout, normw, normb, out, n_nodes);
}